// round 1
// baseline (speedup 1.0000x reference)
#include <cuda_runtime.h>

#define NN 32
#define RESOL 256
#define KK 1024
#define NK (NN * KK)
#define EPSF 1e-6f

// loss kernel tiling
#define CHUNKS 16          // j-chunks per image
#define JPB 64             // j's per block
#define QUARTS 4           // i-dimension split per j
#define IPQ (KK / QUARTS)  // 256 i's per thread

// Scratch (allocation-free rule: __device__ globals)
__device__ float g_src_c[NK * 2];
__device__ float g_trg_c[NK * 2];
__device__ float g_vis[NK];
__device__ float g_loss;
__device__ float g_viscount;

// ---------------------------------------------------------------------------
// Kernel A: decode kp_vis (runtime dtype detection), count visible, zero accums
// ---------------------------------------------------------------------------
__global__ void prep_kernel(const unsigned char* __restrict__ visraw) {
    __shared__ int s_mode;
    if (threadIdx.x == 0) {
        g_loss = 0.0f;
        g_viscount = 0.0f;
        // Detect serialized dtype of the bool array from byte pattern.
        // uint8 bool: ~80% of ALL bytes nonzero (incl. residue 1 mod 4)
        // int32 0/1 : nonzero only at residue 0
        // float 1.0f: bytes {00,00,80,3F} -> nonzero only at residues 2,3
        int r1 = 0, r23 = 0;
        for (int i = 0; i < 4096; i++) {
            unsigned char b = visraw[i];
            if (b) {
                int r = i & 3;
                if (r == 1) r1 = 1;
                else if (r >= 2) r23 = 1;
            }
        }
        s_mode = r1 ? 0 : (r23 ? 2 : 1);  // 0=u8, 1=i32, 2=f32
    }
    __syncthreads();
    const int m = s_mode;
    float cnt = 0.0f;
    for (int i = threadIdx.x; i < NK; i += blockDim.x) {
        bool v;
        if (m == 0)      v = visraw[i] != 0;
        else if (m == 1) v = ((const int*)visraw)[i] != 0;
        else             v = ((const float*)visraw)[i] != 0.0f;
        g_vis[i] = v ? 1.0f : 0.0f;
        if (v) cnt += 1.0f;
    }
    atomicAdd(&g_viscount, cnt);
}

// ---------------------------------------------------------------------------
// Kernel B: bilinear sampling (grid_sample, zeros padding, align_corners=True)
// ---------------------------------------------------------------------------
__device__ __forceinline__ float2 bsample(const float2* __restrict__ flow,
                                          float x, float y) {
    float x0 = floorf(x), y0 = floorf(y);
    float wx = x - x0, wy = y - y0;
    float ax = 0.0f, ay = 0.0f;
#pragma unroll
    for (int dy = 0; dy < 2; dy++) {
#pragma unroll
        for (int dx = 0; dx < 2; dx++) {
            float xi = x0 + (float)dx;
            float yi = y0 + (float)dy;
            bool valid = (xi >= 0.0f) && (xi <= (float)(RESOL - 1)) &&
                         (yi >= 0.0f) && (yi <= (float)(RESOL - 1));
            if (valid) {
                int xc = (int)xi;
                int yc = (int)yi;
                float w = (dx ? wx : 1.0f - wx) * (dy ? wy : 1.0f - wy);
                float2 v = flow[yc * RESOL + xc];
                ax = fmaf(w, v.x, ax);
                ay = fmaf(w, v.y, ay);
            }
        }
    }
    return make_float2(ax, ay);
}

__global__ void sample_kernel(const float* __restrict__ src_flow,
                              const float* __restrict__ trg_flow,
                              const float* __restrict__ src_kp,
                              const float* __restrict__ trg_kp) {
    int idx = blockIdx.x * blockDim.x + threadIdx.x;
    if (idx >= NK) return;
    int n = idx >> 10;  // / KK
    const float2* sf = (const float2*)(src_flow + (size_t)n * RESOL * RESOL * 2);
    const float2* tf = (const float2*)(trg_flow + (size_t)n * RESOL * RESOL * 2);
    float sx = src_kp[idx * 2 + 0], sy = src_kp[idx * 2 + 1];
    float tx = trg_kp[idx * 2 + 0], ty = trg_kp[idx * 2 + 1];
    ((float2*)g_src_c)[idx] = bsample(sf, sx, sy);
    ((float2*)g_trg_c)[idx] = bsample(tf, tx, ty);
}

// ---------------------------------------------------------------------------
// Kernel C: main loss. Block = (n, chunk of 64 j). 256 threads:
//   tid%64 = local j, tid/64 = quarter of the i-range (256 i's per thread).
//   src_c[n] lives in smem; reads are warp-uniform broadcasts.
// loss_j = dist(j,j) + log( sum_i exp(-dist(i,j)) )   (logits <= 0, no shift needed)
// ---------------------------------------------------------------------------
__global__ void __launch_bounds__(256) loss_kernel(const float* __restrict__ kp_wt) {
    __shared__ float2 s_src[KK];
    __shared__ float s_sum[JPB];
    __shared__ float s_djj[JPB];

    const int n = blockIdx.x / CHUNKS;
    const int chunk = blockIdx.x % CHUNKS;
    const int tid = threadIdx.x;

    const float2* srcn = ((const float2*)g_src_c) + n * KK;
    for (int i = tid; i < KK; i += 256) s_src[i] = srcn[i];
    if (tid < JPB) s_sum[tid] = 0.0f;
    __syncthreads();

    const int jl = tid & (JPB - 1);
    const int q = tid >> 6;
    const int j = chunk * JPB + jl;

    const float2 t = ((const float2*)g_trg_c)[n * KK + j];
    const float txe = t.x - EPSF;  // dx = sx - tx + eps = sx - txe
    const float tye = t.y - EPSF;

    float sum = 0.0f;
    float djj = 0.0f;
    const int i0 = q * IPQ;
#pragma unroll 4
    for (int i = i0; i < i0 + IPQ; i++) {
        float2 s = s_src[i];
        float dx = s.x - txe;
        float dy = s.y - tye;
        float ss = fmaf(dx, dx, dy * dy);
        // sqrt via rsqrt (1 MUFU + 1 FMUL); guard against ss==0 -> 0*inf
        float d = ss * rsqrtf(fmaxf(ss, 1e-30f));
        if (i == j) djj = d;
        sum += __expf(-d);  // FMUL + MUFU.EX2
    }

    atomicAdd(&s_sum[jl], sum);
    if (j >= i0 && j < i0 + IPQ) s_djj[jl] = djj;
    __syncthreads();

    if (tid < JPB) {
        const int jg = n * KK + chunk * JPB + tid;
        float total = s_sum[tid];
        float val = (s_djj[tid] + __logf(total)) * g_vis[jg] * kp_wt[jg];
        // reduce 64 -> 2 atomics (threads 0..63 are full warps 0 and 1)
#pragma unroll
        for (int off = 16; off; off >>= 1)
            val += __shfl_down_sync(0xFFFFFFFFu, val, off);
        if ((tid & 31) == 0) atomicAdd(&g_loss, val);
    }
}

// ---------------------------------------------------------------------------
// Kernel D: finalize.  d1 == d2 in the forward pass (stop_gradient is a no-op),
// so the total is 2x a single CE term.
// ---------------------------------------------------------------------------
__global__ void finalize_kernel(float* __restrict__ out) {
    out[0] = 2.0f * g_loss / g_viscount;
}

extern "C" void kernel_launch(void* const* d_in, const int* in_sizes, int n_in,
                              void* d_out, int out_size) {
    (void)in_sizes; (void)n_in; (void)out_size;
    const float* src_flow = (const float*)d_in[0];
    const float* trg_flow = (const float*)d_in[1];
    const float* src_kp   = (const float*)d_in[2];
    const float* trg_kp   = (const float*)d_in[3];
    const unsigned char* kp_vis = (const unsigned char*)d_in[4];
    const float* kp_wt    = (const float*)d_in[5];
    float* out = (float*)d_out;

    prep_kernel<<<1, 256>>>(kp_vis);
    sample_kernel<<<NK / 256, 256>>>(src_flow, trg_flow, src_kp, trg_kp);
    loss_kernel<<<NN * CHUNKS, 256>>>(kp_wt);
    finalize_kernel<<<1, 1>>>(out);
}

// round 2
// speedup vs baseline: 2.5497x; 2.5497x over previous
#include <cuda_runtime.h>

#define NN 32
#define RESOL 256
#define KK 1024
#define NK (NN * KK)
#define EPSF 1e-6f

// loss tiling: block = (n, chunk of 32 j), 256 threads = 32 j x 8 i-quarters
#define CHUNKS 32
#define JPB 32
#define QUARTS 8
#define IPQ (KK / QUARTS)  // 128

// Scratch (__device__ globals: allocation-free rule)
__device__ float g_src_c[NK * 2];
__device__ float g_trg_c[NK * 2];
__device__ float g_loss;
__device__ float g_viscount;
__device__ int g_mode;
__device__ unsigned int g_done;

__device__ __forceinline__ float sqrt_approx(float x) {
    float r;
    asm("sqrt.approx.f32 %0, %1;" : "=f"(r) : "f"(x));
    return r;
}

// ---------------------------------------------------------------------------
// Kernel A: bilinear sampling. Block 0 additionally does vis-dtype detection
// and zeroes the accumulators (all consumed only by the loss kernel, which
// launches strictly after).
// ---------------------------------------------------------------------------
__device__ __forceinline__ float2 bsample(const float2* __restrict__ flow,
                                          float x, float y) {
    float x0 = floorf(x), y0 = floorf(y);
    float wx = x - x0, wy = y - y0;
    float ax = 0.0f, ay = 0.0f;
#pragma unroll
    for (int dy = 0; dy < 2; dy++) {
#pragma unroll
        for (int dx = 0; dx < 2; dx++) {
            float xi = x0 + (float)dx;
            float yi = y0 + (float)dy;
            bool valid = (xi >= 0.0f) && (xi <= (float)(RESOL - 1)) &&
                         (yi >= 0.0f) && (yi <= (float)(RESOL - 1));
            if (valid) {
                float w = (dx ? wx : 1.0f - wx) * (dy ? wy : 1.0f - wy);
                float2 v = flow[(int)yi * RESOL + (int)xi];
                ax = fmaf(w, v.x, ax);
                ay = fmaf(w, v.y, ay);
            }
        }
    }
    return make_float2(ax, ay);
}

__global__ void __launch_bounds__(256) sample_kernel(
    const float* __restrict__ src_flow, const float* __restrict__ trg_flow,
    const float* __restrict__ src_kp, const float* __restrict__ trg_kp,
    const unsigned char* __restrict__ visraw) {
    if (blockIdx.x == 0) {
        // Parallel dtype detection over the first 4096 bytes of kp_vis.
        // uint8 bool: nonzero bytes at residue 1 (and everywhere)
        // int32 0/1 : nonzero only at residue 0
        // float 1.0f: bytes {00,00,80,3F} -> nonzero only at residues 2,3
        __shared__ int s_r1, s_r23;
        if (threadIdx.x == 0) {
            s_r1 = 0; s_r23 = 0;
            g_loss = 0.0f; g_viscount = 0.0f; g_done = 0u;
        }
        __syncthreads();
        int r1 = 0, r23 = 0;
        const int base = threadIdx.x * 16;
#pragma unroll
        for (int k = 0; k < 16; k++) {
            unsigned char b = visraw[base + k];
            if (b) {
                int r = (base + k) & 3;
                if (r == 1) r1 = 1;
                else if (r >= 2) r23 = 1;
            }
        }
        if (r1) atomicOr(&s_r1, 1);
        if (r23) atomicOr(&s_r23, 1);
        __syncthreads();
        if (threadIdx.x == 0)
            g_mode = s_r1 ? 0 : (s_r23 ? 2 : 1);  // 0=u8, 1=i32, 2=f32
    }

    int idx = blockIdx.x * blockDim.x + threadIdx.x;
    int n = idx >> 10;
    const float2* sf = (const float2*)(src_flow + (size_t)n * RESOL * RESOL * 2);
    const float2* tf = (const float2*)(trg_flow + (size_t)n * RESOL * RESOL * 2);
    float2 skp = ((const float2*)src_kp)[idx];
    float2 tkp = ((const float2*)trg_kp)[idx];
    ((float2*)g_src_c)[idx] = bsample(sf, skp.x, skp.y);
    ((float2*)g_trg_c)[idx] = bsample(tf, tkp.x, tkp.y);
}

// ---------------------------------------------------------------------------
// Kernel B: loss + fused finalize.
// loss_j = d(j,j) + log( sum_i exp(-d(i,j)) )   (logits <= 0, no max-shift)
// d1 == d2 in the forward pass (stop_gradient is a no-op) -> final x2.
// ---------------------------------------------------------------------------
__global__ void __launch_bounds__(256) loss_kernel(
    const unsigned char* __restrict__ visraw,
    const float* __restrict__ kp_wt, float* __restrict__ out) {
    __shared__ float2 s_src[KK];
    __shared__ float s_sum[JPB];

    const int n = blockIdx.x >> 5;        // / CHUNKS
    const int chunk = blockIdx.x & 31;    // % CHUNKS
    const int tid = threadIdx.x;

    // stage src_c[n] (8 KB) into smem via float4
    {
        const float4* srcn4 = (const float4*)(g_src_c + n * KK * 2);
        float4* s4 = (float4*)s_src;
#pragma unroll
        for (int k = 0; k < 2; k++) s4[tid + 256 * k] = srcn4[tid + 256 * k];
    }
    if (tid < JPB) s_sum[tid] = 0.0f;
    __syncthreads();

    const int jl = tid & (JPB - 1);
    const int q = tid >> 5;               // warp id == i-quarter
    const int j = chunk * JPB + jl;

    const float2 t = ((const float2*)g_trg_c)[n * KK + j];
    const float txe = t.x - EPSF;  // dx = sx - tx + eps
    const float tye = t.y - EPSF;

    float sum = 0.0f;
    const int i0 = q * IPQ;
#pragma unroll 8
    for (int i = i0; i < i0 + IPQ; i++) {
        float2 s = s_src[i];               // warp-uniform broadcast
        float dx = s.x - txe;
        float dy = s.y - tye;
        float d = sqrt_approx(fmaf(dx, dx, dy * dy));
        sum += __expf(-d);
    }
    atomicAdd(&s_sum[jl], sum);
    __syncthreads();

    if (tid < JPB) {
        // diagonal term (thread tid's own t is trg[j] since q==0 here)
        float2 s = s_src[j];
        float dx = s.x - txe;
        float dy = s.y - tye;
        float djj = sqrt_approx(fmaf(dx, dx, dy * dy));

        const int jg = n * KK + j;
        const int m = g_mode;
        bool v;
        if (m == 0)      v = visraw[jg] != 0;
        else if (m == 1) v = ((const int*)visraw)[jg] != 0;
        else             v = ((const float*)visraw)[jg] != 0.0f;
        float visf = v ? 1.0f : 0.0f;

        float val = (djj + __logf(s_sum[tid])) * visf * kp_wt[jg];
#pragma unroll
        for (int off = 16; off; off >>= 1) {
            val  += __shfl_down_sync(0xFFFFFFFFu, val, off);
            visf += __shfl_down_sync(0xFFFFFFFFu, visf, off);
        }
        if (tid == 0) {
            atomicAdd(&g_loss, val);
            atomicAdd(&g_viscount, visf);
            __threadfence();
            unsigned int ticket = atomicAdd(&g_done, 1u);
            if (ticket == gridDim.x - 1) {
                float L = *((volatile float*)&g_loss);
                float V = *((volatile float*)&g_viscount);
                out[0] = 2.0f * L / V;
            }
        }
    }
}

extern "C" void kernel_launch(void* const* d_in, const int* in_sizes, int n_in,
                              void* d_out, int out_size) {
    (void)in_sizes; (void)n_in; (void)out_size;
    const float* src_flow = (const float*)d_in[0];
    const float* trg_flow = (const float*)d_in[1];
    const float* src_kp   = (const float*)d_in[2];
    const float* trg_kp   = (const float*)d_in[3];
    const unsigned char* kp_vis = (const unsigned char*)d_in[4];
    const float* kp_wt    = (const float*)d_in[5];
    float* out = (float*)d_out;

    sample_kernel<<<NK / 256, 256>>>(src_flow, trg_flow, src_kp, trg_kp, kp_vis);
    loss_kernel<<<NN * CHUNKS, 256>>>(kp_vis, kp_wt, out);
}